// round 15
// baseline (speedup 1.0000x reference)
#include <cuda_runtime.h>
#include <cuda_fp16.h>
#include <math.h>
#include <stdint.h>

#define N 2048
#define HIDDEN 256
#define HEADS 8
#define DK 32
#define NSPLIT 2
#define KSPAN (N / NSPLIT)
#define NCHUNK (N / 64)
#define BSTR 72   // bias smem row stride in halves

#define PROJ_BLOCKS (32 * 4 * 3)          // 384
#define BIAS_BLOCKS ((N * N / 4) / 256)   // 4096

// -------------------- scratch (__device__ globals; no allocs allowed) -----
__device__ __half g_bias[N * N];                   // 8 MB fp16 pair bias
__device__ float g_qh[HEADS * N * DK];             // head-major projected q (scaled)
__device__ uint32_t g_kf[HEADS * NCHUNK * 1024];   // fragment-major fp16 K
__device__ uint32_t g_vf[HEADS * NCHUNK * 1024];   // fragment-major fp16 V
// split-K partials (fp16 pav -> 2 MB)
__device__ float  g_pm[NSPLIT * HEADS * N];
__device__ float  g_pl[NSPLIT * HEADS * N];
__device__ __half g_pav[NSPLIT * HEADS * N * DK];

// -------------------- helpers ---------------------------------------------
__device__ __forceinline__ uint32_t f2tf(float f) {
    uint32_t u;
    asm("cvt.rna.tf32.f32 %0, %1;" : "=r"(u) : "f"(f));
    return u;
}

__device__ __forceinline__ uint32_t packh2(float lo, float hi) {
    __half2 h = __floats2half2_rn(lo, hi);
    return *reinterpret_cast<uint32_t*>(&h);
}

__device__ __forceinline__ void mma_tf32(float& d0, float& d1, float& d2, float& d3,
                                         uint32_t a0, uint32_t a1, uint32_t a2, uint32_t a3,
                                         uint32_t b0, uint32_t b1)
{
    asm volatile("mma.sync.aligned.m16n8k8.row.col.f32.tf32.tf32.f32 "
                 "{%0,%1,%2,%3}, {%4,%5,%6,%7}, {%8,%9}, {%0,%1,%2,%3};"
                 : "+f"(d0), "+f"(d1), "+f"(d2), "+f"(d3)
                 : "r"(a0), "r"(a1), "r"(a2), "r"(a3), "r"(b0), "r"(b1));
}

__device__ __forceinline__ void mma_f16(float& d0, float& d1, float& d2, float& d3,
                                        uint32_t a0, uint32_t a1, uint32_t a2, uint32_t a3,
                                        uint32_t b0, uint32_t b1)
{
    asm volatile("mma.sync.aligned.m16n8k16.row.col.f32.f16.f16.f32 "
                 "{%0,%1,%2,%3}, {%4,%5,%6,%7}, {%8,%9}, {%0,%1,%2,%3};"
                 : "+f"(d0), "+f"(d1), "+f"(d2), "+f"(d3)
                 : "r"(a0), "r"(a1), "r"(a2), "r"(a3), "r"(b0), "r"(b1));
}

__device__ __forceinline__ void cp16(uint32_t smem_dst, const void* gsrc) {
    asm volatile("cp.async.cg.shared.global [%0], [%1], 16;"
                 :: "r"(smem_dst), "l"(gsrc));
}

// K fragment word index (fp16x2 packed over d-pairs): B-frag of m16n8k16
__device__ __forceinline__ int kaddr16(int key, int d) {
    return ((d >> 4) * 8 + (key >> 3)) * 64 + ((key & 7) * 4 + ((d & 7) >> 1)) * 2 + ((d >> 3) & 1);
}
// V fragment half index (fp16x2 packed over key-pairs)
__device__ __forceinline__ int vaddr16h(int key, int d) {
    return ((((key >> 4) * 4 + (d >> 3)) * 32 + (d & 7) * 4 + ((key & 7) >> 1)) * 2
            + ((key >> 3) & 1)) * 2 + (key & 1);
}

// -------------------- tf32 projection GEMM body ----------------------------
// mode 0: head-major scaled (Q)   mode 2: K fp16 fragment-major
// mode 3: V fp16 fragment-major
__device__ __forceinline__ void proj_body(const float* __restrict__ A,
                                          const float* __restrict__ W,
                                          const float* __restrict__ bias,
                                          float* __restrict__ out,
                                          float scale, int mode, int m0, int n0)
{
    __shared__ uint4 AF[2][16 * 32];
    __shared__ uint2 BF[2][32 * 32];

    const int t    = threadIdx.x;
    const int lane = t & 31;
    const int w    = t >> 5;
    const int q    = lane & 3;
    const int g    = lane >> 2;
    const int mf    = w >> 1;
    const int nhalf = w & 1;

    float acc[4][4];
    #pragma unroll
    for (int j = 0; j < 4; j++)
        #pragma unroll
        for (int e = 0; e < 4; e++) acc[j][e] = 0.f;

    const int a_m0 = t >> 3,         a_k4_0 = t & 7;
    const int a_m1 = (t + 256) >> 3, a_k4_1 = (t + 256) & 7;
    const int b_k0 = t >> 4,         b_n4_0 = t & 15;
    const int b_k1 = (t + 256) >> 4, b_n4_1 = (t + 256) & 15;

    float4 ra0, ra1, rb0, rb1;
    ra0 = *(const float4*)&A[(size_t)(m0 + a_m0) * 256 + 0 + a_k4_0 * 4];
    ra1 = *(const float4*)&A[(size_t)(m0 + a_m1) * 256 + 0 + a_k4_1 * 4];
    rb0 = *(const float4*)&W[(size_t)(0 + b_k0) * 256 + n0 + b_n4_0 * 4];
    rb1 = *(const float4*)&W[(size_t)(0 + b_k1) * 256 + n0 + b_n4_1 * 4];

    for (int c = 0; c < 8; c++) {
        const int buf = c & 1;
        {
            #pragma unroll
            for (int p = 0; p < 2; p++) {
                int m  = p ? a_m1 : a_m0;
                int k4 = p ? a_k4_1 : a_k4_0;
                float4 v = p ? ra1 : ra0;
                int frag = (m >> 4) * 4 + (k4 >> 1);
                int idx  = (k4 & 1) * 2 + ((m & 15) >> 3);
                uint32_t* dst = (uint32_t*)&AF[buf][frag * 32 + ((m & 7) * 4)];
                dst[0 * 4 + idx] = f2tf(v.x);
                dst[1 * 4 + idx] = f2tf(v.y);
                dst[2 * 4 + idx] = f2tf(v.z);
                dst[3 * 4 + idx] = f2tf(v.w);
            }
            #pragma unroll
            for (int p = 0; p < 2; p++) {
                int k  = p ? b_k1 : b_k0;
                int n4 = p ? b_n4_1 : b_n4_0;
                float4 v = p ? rb1 : rb0;
                int frag = (n4 >> 1) * 4 + (k >> 3);
                int hi   = (k >> 2) & 1;
                uint32_t* dst = (uint32_t*)&BF[buf][frag * 32 + (n4 & 1) * 16 + (k & 3)];
                dst[0 * 8 + hi] = f2tf(v.x);
                dst[1 * 8 + hi] = f2tf(v.y);
                dst[2 * 8 + hi] = f2tf(v.z);
                dst[3 * 8 + hi] = f2tf(v.w);
            }
        }
        __syncthreads();

        if (c < 7) {
            int kt = (c + 1) * 32;
            ra0 = *(const float4*)&A[(size_t)(m0 + a_m0) * 256 + kt + a_k4_0 * 4];
            ra1 = *(const float4*)&A[(size_t)(m0 + a_m1) * 256 + kt + a_k4_1 * 4];
            rb0 = *(const float4*)&W[(size_t)(kt + b_k0) * 256 + n0 + b_n4_0 * 4];
            rb1 = *(const float4*)&W[(size_t)(kt + b_k1) * 256 + n0 + b_n4_1 * 4];
        }

        #pragma unroll
        for (int ks = 0; ks < 4; ks++) {
            uint4 a = AF[buf][(mf * 4 + ks) * 32 + lane];
            #pragma unroll
            for (int j = 0; j < 4; j++) {
                uint2 b = BF[buf][((nhalf * 4 + j) * 4 + ks) * 32 + lane];
                mma_tf32(acc[j][0], acc[j][1], acc[j][2], acc[j][3],
                         a.x, a.y, a.z, a.w, b.x, b.y);
            }
        }
    }

    const int row0 = m0 + mf * 16 + g;
    const int key0 = mf * 16 + g;
    const int ck   = m0 >> 6;
    #pragma unroll
    for (int j = 0; j < 4; j++) {
        int col = n0 + nhalf * 32 + j * 8 + 2 * q;
        float2 bz = *(const float2*)&bias[col];
        float v00 = acc[j][0] + bz.x, v01 = acc[j][1] + bz.y;
        float v10 = acc[j][2] + bz.x, v11 = acc[j][3] + bz.y;
        if (mode == 0) {
            v00 *= scale; v01 *= scale; v10 *= scale; v11 *= scale;
            size_t base = (size_t)(col >> 5) * ((size_t)N * 32) + (col & 31);
            *(float2*)&out[base + (size_t)row0 * 32]       = make_float2(v00, v01);
            *(float2*)&out[base + (size_t)(row0 + 8) * 32] = make_float2(v10, v11);
        } else {
            int hh = col >> 5, dd = col & 31;
            if (mode == 2) {
                uint32_t* KD = &g_kf[((size_t)hh * NCHUNK + ck) * 1024];
                KD[kaddr16(key0,     dd)] = packh2(v00, v01);
                KD[kaddr16(key0 + 8, dd)] = packh2(v10, v11);
            } else {
                __half* VD = (__half*)&g_vf[((size_t)hh * NCHUNK + ck) * 1024];
                VD[vaddr16h(key0,     dd)]     = __float2half_rn(v00);
                VD[vaddr16h(key0,     dd + 1)] = __float2half_rn(v01);
                VD[vaddr16h(key0 + 8, dd)]     = __float2half_rn(v10);
                VD[vaddr16h(key0 + 8, dd + 1)] = __float2half_rn(v11);
            }
        }
    }
}

// -------------------- fused prep: QKV projections + pair-bias --------------
__global__ __launch_bounds__(256) void prep_kernel(
    const float* __restrict__ q, const float* __restrict__ k, const float* __restrict__ v,
    const float* __restrict__ Wq, const float* __restrict__ Wk, const float* __restrict__ Wv,
    const float* __restrict__ bq, const float* __restrict__ bk, const float* __restrict__ bv,
    float* __restrict__ oq, float scale,
    const int* __restrict__ label, const float* __restrict__ dist,
    const float* __restrict__ contact,
    const float* __restrict__ Wd1, const float* __restrict__ bd1,
    const float* __restrict__ Wd2, const float* __restrict__ bd2,
    const float* __restrict__ Wc1, const float* __restrict__ bc1,
    const float* __restrict__ Wc2, const float* __restrict__ bc2)
{
    const int bid = blockIdx.x;
    if (bid < PROJ_BLOCKS) {
        const int pz  = bid >> 7;
        const int rem = bid & 127;
        const int m0  = (rem & 31) * 64;
        const int n0  = (rem >> 5) * 64;
        if (pz == 0)      proj_body(q, Wq, bq, oq,      scale, 0, m0, n0);
        else if (pz == 1) proj_body(k, Wk, bk, nullptr, 1.f,   2, m0, n0);
        else              proj_body(v, Wv, bv, nullptr, 1.f,   3, m0, n0);
        return;
    }

    // ---- bias path ----
    __shared__ float4 cf;
    if (threadIdx.x == 0) {
        float am = 0.f, al = 0.f, c0 = bd2[0] + bc2[0], cm = 0.f;
        #pragma unroll
        for (int h = 0; h < 16; h++) {
            am += Wd1[h]      * Wd2[h];
            al += Wd1[16 + h] * Wd2[h];
            c0 += bd1[h]      * Wd2[h];
            cm += Wc1[h]      * Wc2[h];
            al += Wc1[16 + h] * Wc2[h];
            c0 += bc1[h]      * Wc2[h];
        }
        cf = make_float4(am, cm, al, c0);
    }
    __syncthreads();
    const float am = cf.x, cm = cf.y, al = cf.z, c0 = cf.w;

    int i = (bid - PROJ_BLOCKS) * 256 + threadIdx.x;
    float4 dm = ((const float4*)dist)[i];
    float4 cv = ((const float4*)contact)[i];
    int4   lb = ((const int4*)label)[i];
    float ox = fmaf(am, dm.x, fmaf(cm, cv.x, fmaf(al, (float)lb.x, c0)));
    float oy = fmaf(am, dm.y, fmaf(cm, cv.y, fmaf(al, (float)lb.y, c0)));
    float oz = fmaf(am, dm.z, fmaf(cm, cv.z, fmaf(al, (float)lb.z, c0)));
    float ow = fmaf(am, dm.w, fmaf(cm, cv.w, fmaf(al, (float)lb.w, c0)));
    uint2 r;
    r.x = packh2(ox, oy);
    r.y = packh2(oz, ow);
    ((uint2*)g_bias)[i] = r;
}

// -------------------- O-projection with fused 2-way split-K combine --------
// A gathered from fp16 partials: pv loads are uint2 (4 halfs), unpacked and
// combined with per-(row,head) weights from smem.
__global__ __launch_bounds__(256) void o_proj_fused(const float* __restrict__ W,
                                                    const float* __restrict__ bo,
                                                    float* __restrict__ out)
{
    __shared__ uint4 AF[2][16 * 32];
    __shared__ uint2 BF[2][32 * 32];
    __shared__ float2 WC[64][8];

    const int t    = threadIdx.x;
    const int lane = t & 31;
    const int w    = t >> 5;
    const int q    = lane & 3;
    const int g    = lane >> 2;
    const int m0   = blockIdx.x * 64;
    const int n0   = blockIdx.y * 64;
    const int mf    = w >> 1;
    const int nhalf = w & 1;

    #pragma unroll
    for (int p = 0; p < 2; p++) {
        int idx = t + p * 256;
        int r = idx >> 3, hh = idx & 7;
        int row = m0 + r;
        float pm0 = g_pm[(0 * HEADS + hh) * N + row];
        float pm1 = g_pm[(1 * HEADS + hh) * N + row];
        float pl0 = g_pl[(0 * HEADS + hh) * N + row];
        float pl1 = g_pl[(1 * HEADS + hh) * N + row];
        float M = fmaxf(pm0, pm1);
        float w0 = __expf(pm0 - M), w1 = __expf(pm1 - M);
        float inv = 1.f / (pl0 * w0 + pl1 * w1);
        WC[r][hh] = make_float2(w0 * inv, w1 * inv);
    }
    __syncthreads();

    float acc[4][4];
    #pragma unroll
    for (int j = 0; j < 4; j++)
        #pragma unroll
        for (int e = 0; e < 4; e++) acc[j][e] = 0.f;

    const int a_m0 = t >> 3,         a_k4_0 = t & 7;
    const int a_m1 = (t + 256) >> 3, a_k4_1 = (t + 256) & 7;
    const int b_k0 = t >> 4,         b_n4_0 = t & 15;
    const int b_k1 = (t + 256) >> 4, b_n4_1 = (t + 256) & 15;

    uint2 pv[2][2];        // 4 fp16 values per (slot, split)
    float4 rb0, rb1;
    #pragma unroll
    for (int p = 0; p < 2; p++) {
        int m  = p ? a_m1 : a_m0;
        int d0 = (p ? a_k4_1 : a_k4_0) * 4;
        #pragma unroll
        for (int s = 0; s < NSPLIT; s++)
            pv[p][s] = *(const uint2*)&g_pav[(((size_t)(s * HEADS + 0)) * N + m0 + m) * DK + d0];
    }
    rb0 = *(const float4*)&W[(size_t)(0 + b_k0) * 256 + n0 + b_n4_0 * 4];
    rb1 = *(const float4*)&W[(size_t)(0 + b_k1) * 256 + n0 + b_n4_1 * 4];

    for (int c = 0; c < 8; c++) {
        const int buf = c & 1;
        {
            #pragma unroll
            for (int p = 0; p < 2; p++) {
                int m  = p ? a_m1 : a_m0;
                int k4 = p ? a_k4_1 : a_k4_0;
                float2 wc = WC[m][c];
                float2 a0 = __half22float2(*(const __half2*)&pv[p][0].x);
                float2 a1 = __half22float2(*(const __half2*)&pv[p][0].y);
                float2 b0 = __half22float2(*(const __half2*)&pv[p][1].x);
                float2 b1 = __half22float2(*(const __half2*)&pv[p][1].y);
                float4 v;
                v.x = wc.x * a0.x + wc.y * b0.x;
                v.y = wc.x * a0.y + wc.y * b0.y;
                v.z = wc.x * a1.x + wc.y * b1.x;
                v.w = wc.x * a1.y + wc.y * b1.y;
                int frag = (m >> 4) * 4 + (k4 >> 1);
                int idx  = (k4 & 1) * 2 + ((m & 15) >> 3);
                uint32_t* dst = (uint32_t*)&AF[buf][frag * 32 + ((m & 7) * 4)];
                dst[0 * 4 + idx] = f2tf(v.x);
                dst[1 * 4 + idx] = f2tf(v.y);
                dst[2 * 4 + idx] = f2tf(v.z);
                dst[3 * 4 + idx] = f2tf(v.w);
            }
            #pragma unroll
            for (int p = 0; p < 2; p++) {
                int k  = p ? b_k1 : b_k0;
                int n4 = p ? b_n4_1 : b_n4_0;
                float4 v = p ? rb1 : rb0;
                int frag = (n4 >> 1) * 4 + (k >> 3);
                int hi   = (k >> 2) & 1;
                uint32_t* dst = (uint32_t*)&BF[buf][frag * 32 + (n4 & 1) * 16 + (k & 3)];
                dst[0 * 8 + hi] = f2tf(v.x);
                dst[1 * 8 + hi] = f2tf(v.y);
                dst[2 * 8 + hi] = f2tf(v.z);
                dst[3 * 8 + hi] = f2tf(v.w);
            }
        }
        __syncthreads();

        if (c < 7) {
            int hh = c + 1;
            #pragma unroll
            for (int p = 0; p < 2; p++) {
                int m  = p ? a_m1 : a_m0;
                int d0 = (p ? a_k4_1 : a_k4_0) * 4;
                #pragma unroll
                for (int s = 0; s < NSPLIT; s++)
                    pv[p][s] = *(const uint2*)&g_pav[(((size_t)(s * HEADS + hh)) * N + m0 + m) * DK + d0];
            }
            int kt = hh * 32;
            rb0 = *(const float4*)&W[(size_t)(kt + b_k0) * 256 + n0 + b_n4_0 * 4];
            rb1 = *(const float4*)&W[(size_t)(kt + b_k1) * 256 + n0 + b_n4_1 * 4];
        }

        #pragma unroll
        for (int ks = 0; ks < 4; ks++) {
            uint4 a = AF[buf][(mf * 4 + ks) * 32 + lane];
            #pragma unroll
            for (int j = 0; j < 4; j++) {
                uint2 b = BF[buf][((nhalf * 4 + j) * 4 + ks) * 32 + lane];
                mma_tf32(acc[j][0], acc[j][1], acc[j][2], acc[j][3],
                         a.x, a.y, a.z, a.w, b.x, b.y);
            }
        }
    }

    const int row0 = m0 + mf * 16 + g;
    #pragma unroll
    for (int j = 0; j < 4; j++) {
        int col = n0 + nhalf * 32 + j * 8 + 2 * q;
        float2 bz = *(const float2*)&bo[col];
        *(float2*)&out[(size_t)row0 * 256 + col] =
            make_float2(acc[j][0] + bz.x, acc[j][1] + bz.y);
        *(float2*)&out[(size_t)(row0 + 8) * 256 + col] =
            make_float2(acc[j][2] + bz.x, acc[j][3] + bz.y);
    }
}

// -------------------- fp16 flash attention (R9 shape, NSPLIT=2) ------------
__global__ __launch_bounds__(128) void attn_mma_kernel()
{
    extern __shared__ uint32_t dsm[];
    uint32_t* KBb = dsm;                     // [2][1024]
    uint32_t* VBb = dsm + 2048;              // [2][1024]
    __half*   BSb = (__half*)(dsm + 4096);   // [2][64*BSTR]

    const int tid  = threadIdx.x;
    const int lane = tid & 31;
    const int warp = tid >> 5;
    const int q    = lane & 3;
    const int g    = lane >> 2;
    const int h  = blockIdx.y;
    const int z  = blockIdx.z;
    const int q0 = blockIdx.x * 64;
    const int wr0 = warp * 16;
    const int row = q0 + wr0 + g;

    uint32_t qa[2][4];
    {
        const float* q0p = &g_qh[((size_t)h * N + row) * DK];
        const float* q8p = q0p + 8 * DK;
        #pragma unroll
        for (int ks = 0; ks < 2; ks++) {
            int d = ks * 16 + 2 * q;
            qa[ks][0] = packh2(q0p[d],     q0p[d + 1]);
            qa[ks][1] = packh2(q8p[d],     q8p[d + 1]);
            qa[ks][2] = packh2(q0p[d + 8], q0p[d + 9]);
            qa[ks][3] = packh2(q8p[d + 8], q8p[d + 9]);
        }
    }

    float o[4][4];
    #pragma unroll
    for (int n = 0; n < 4; n++)
        #pragma unroll
        for (int e = 0; e < 4; e++) o[n][e] = 0.f;

    float m0 = -INFINITY, m8 = -INFINITY, l0 = 0.f, l8 = 0.f;

    const int ck0 = (z * KSPAN) / 64;
    const int nch = KSPAN / 64;

    auto fill = [&](int buf, int ck) {
        const uint4* ks = (const uint4*)&g_kf[(size_t)(h * NCHUNK + ck) * 1024];
        const uint4* vs = (const uint4*)&g_vf[(size_t)(h * NCHUNK + ck) * 1024];
        #pragma unroll
        for (int i = 0; i < 2; i++) {
            int idx = i * 128 + tid;
            cp16((uint32_t)__cvta_generic_to_shared(&KBb[buf * 1024 + idx * 4]), ks + idx);
            cp16((uint32_t)__cvta_generic_to_shared(&VBb[buf * 1024 + idx * 4]), vs + idx);
        }
        const __half* bsrc = &g_bias[(size_t)q0 * N + ck * 64];
        __half* bdst = &BSb[buf * 64 * BSTR];
        #pragma unroll
        for (int i = 0; i < 4; i++) {
            int idx = i * 128 + tid;
            int r = idx >> 3, c8 = idx & 7;
            cp16((uint32_t)__cvta_generic_to_shared(&bdst[r * BSTR + c8 * 8]),
                 &bsrc[(size_t)r * N + c8 * 8]);
        }
    };

    fill(0, ck0);
    asm volatile("cp.async.commit_group;");

    for (int cc = 0; cc < nch; cc++) {
        const int cur = cc & 1;

        if (cc + 1 < nch) {
            fill(1 - cur, ck0 + cc + 1);
            asm volatile("cp.async.commit_group;");
            asm volatile("cp.async.wait_group 1;");
        } else {
            asm volatile("cp.async.wait_group 0;");
        }
        __syncthreads();

        const uint32_t* KBc = &KBb[cur * 1024];
        const uint32_t* VBc = &VBb[cur * 1024];
        const __half*   BSc = &BSb[cur * 64 * BSTR];

        float s[8][4];
        #pragma unroll
        for (int j = 0; j < 8; j++)
            #pragma unroll
            for (int e = 0; e < 4; e++) s[j][e] = 0.f;

        #pragma unroll
        for (int ks = 0; ks < 2; ks++) {
            #pragma unroll
            for (int j = 0; j < 8; j++) {
                uint2 b = *(const uint2*)&KBc[((ks * 8 + j) * 32 + lane) * 2];
                mma_f16(s[j][0], s[j][1], s[j][2], s[j][3],
                        qa[ks][0], qa[ks][1], qa[ks][2], qa[ks][3], b.x, b.y);
            }
        }

        {
            const __half* br0 = &BSc[(wr0 + g) * BSTR];
            const __half* br8 = br0 + 8 * BSTR;
            #pragma unroll
            for (int j = 0; j < 8; j++) {
                float2 b0 = __half22float2(*(const __half2*)&br0[8 * j + 2 * q]);
                float2 b8 = __half22float2(*(const __half2*)&br8[8 * j + 2 * q]);
                s[j][0] += b0.x; s[j][1] += b0.y;
                s[j][2] += b8.x; s[j][3] += b8.y;
            }
        }

        float mx0 = s[0][0], mx8 = s[0][2];
        #pragma unroll
        for (int j = 0; j < 8; j++) {
            mx0 = fmaxf(mx0, fmaxf(s[j][0], s[j][1]));
            mx8 = fmaxf(mx8, fmaxf(s[j][2], s[j][3]));
        }
        mx0 = fmaxf(mx0, __shfl_xor_sync(0xffffffffu, mx0, 1));
        mx0 = fmaxf(mx0, __shfl_xor_sync(0xffffffffu, mx0, 2));
        mx8 = fmaxf(mx8, __shfl_xor_sync(0xffffffffu, mx8, 1));
        mx8 = fmaxf(mx8, __shfl_xor_sync(0xffffffffu, mx8, 2));

        float mn0 = fmaxf(m0, mx0), mn8 = fmaxf(m8, mx8);
        float c0 = __expf(m0 - mn0), c8 = __expf(m8 - mn8);
        m0 = mn0; m8 = mn8;
        l0 *= c0;  l8 *= c8;
        #pragma unroll
        for (int n = 0; n < 4; n++) {
            o[n][0] *= c0; o[n][1] *= c0;
            o[n][2] *= c8; o[n][3] *= c8;
        }

        float p[8][4];
        #pragma unroll
        for (int j = 0; j < 8; j++) {
            p[j][0] = __expf(s[j][0] - m0);
            p[j][1] = __expf(s[j][1] - m0);
            p[j][2] = __expf(s[j][2] - m8);
            p[j][3] = __expf(s[j][3] - m8);
            l0 += p[j][0] + p[j][1];
            l8 += p[j][2] + p[j][3];
        }

        #pragma unroll
        for (int kk = 0; kk < 4; kk++) {
            uint32_t a0 = packh2(p[2 * kk][0],     p[2 * kk][1]);
            uint32_t a1 = packh2(p[2 * kk][2],     p[2 * kk][3]);
            uint32_t a2 = packh2(p[2 * kk + 1][0], p[2 * kk + 1][1]);
            uint32_t a3 = packh2(p[2 * kk + 1][2], p[2 * kk + 1][3]);
            #pragma unroll
            for (int n = 0; n < 4; n++) {
                uint2 b = *(const uint2*)&VBc[((kk * 4 + n) * 32 + lane) * 2];
                mma_f16(o[n][0], o[n][1], o[n][2], o[n][3], a0, a1, a2, a3, b.x, b.y);
            }
        }
        __syncthreads();
    }

    l0 += __shfl_xor_sync(0xffffffffu, l0, 1);
    l0 += __shfl_xor_sync(0xffffffffu, l0, 2);
    l8 += __shfl_xor_sync(0xffffffffu, l8, 1);
    l8 += __shfl_xor_sync(0xffffffffu, l8, 2);

    const int rid = (z * HEADS + h) * N + q0 + wr0 + g;
    if (q == 0) {
        g_pm[rid] = m0;     g_pl[rid] = l0;
        g_pm[rid + 8] = m8; g_pl[rid + 8] = l8;
    }
    // fp16 partial accumulators: word w holds halfs {2w, 2w+1}; thread q
    // owns halfs 8n+2q -> word 4n+q.
    uint32_t* pav0 = (uint32_t*)&g_pav[(size_t)rid * DK];
    uint32_t* pav8 = (uint32_t*)&g_pav[(size_t)(rid + 8) * DK];
    #pragma unroll
    for (int n = 0; n < 4; n++) {
        pav0[4 * n + q] = packh2(o[n][0], o[n][1]);
        pav8[4 * n + q] = packh2(o[n][2], o[n][3]);
    }
}

// -------------------- launch ------------------------------------------------
extern "C" void kernel_launch(void* const* d_in, const int* in_sizes, int n_in,
                              void* d_out, int out_size)
{
    const int*   label   = (const int*)  d_in[0];
    const float* dist    = (const float*)d_in[1];
    const float* contact = (const float*)d_in[2];
    const float* q       = (const float*)d_in[3];
    const float* k       = (const float*)d_in[4];
    const float* v       = (const float*)d_in[5];
    const float* Wq = (const float*)d_in[6];  const float* bq = (const float*)d_in[7];
    const float* Wk = (const float*)d_in[8];  const float* bk = (const float*)d_in[9];
    const float* Wv = (const float*)d_in[10]; const float* bv = (const float*)d_in[11];
    const float* Wo = (const float*)d_in[12]; const float* bo = (const float*)d_in[13];
    const float* Wd1 = (const float*)d_in[14]; const float* bd1 = (const float*)d_in[15];
    const float* Wd2 = (const float*)d_in[16]; const float* bd2 = (const float*)d_in[17];
    const float* Wc1 = (const float*)d_in[18]; const float* bc1 = (const float*)d_in[19];
    const float* Wc2 = (const float*)d_in[20]; const float* bc2 = (const float*)d_in[21];
    float* out = (float*)d_out;

    float* p_qh;
    cudaGetSymbolAddress((void**)&p_qh, g_qh);

    const float scale = 1.f / sqrtf((float)DK);
    prep_kernel<<<PROJ_BLOCKS + BIAS_BLOCKS, 256>>>(
        q, k, v, Wq, Wk, Wv, bq, bk, bv, p_qh, scale,
        label, dist, contact, Wd1, bd1, Wd2, bd2, Wc1, bc1, Wc2, bc2);

    const int attn_smem = 4096 * 4 + 2 * 64 * BSTR * 2;   // 34816 B
    static int smem_set = 0;
    if (!smem_set) {
        cudaFuncSetAttribute(attn_mma_kernel,
                             cudaFuncAttributeMaxDynamicSharedMemorySize, attn_smem);
        smem_set = 1;
    }
    attn_mma_kernel<<<dim3(N / 64, HEADS, NSPLIT), 128, attn_smem>>>();

    o_proj_fused<<<dim3(N / 64, HIDDEN / 64), 256>>>(Wo, bo, out);
}

// round 16
// speedup vs baseline: 1.0325x; 1.0325x over previous
#include <cuda_runtime.h>
#include <cuda_fp16.h>
#include <math.h>
#include <stdint.h>

#define N 2048
#define HIDDEN 256
#define HEADS 8
#define DK 32
#define NSPLIT 2
#define KSPAN (N / NSPLIT)
#define NCHUNK (N / 64)
#define BSTR 72   // bias smem row stride in halves

#define PROJ_BLOCKS (32 * 4 * 3)               // 384
#define BIAS_ILP 4
#define BIAS_BLOCKS ((N * N / 4) / (256 * BIAS_ILP))   // 1024

// -------------------- scratch (__device__ globals; no allocs allowed) -----
__device__ __half g_bias[N * N];                   // 8 MB fp16 pair bias
__device__ float g_qh[HEADS * N * DK];             // head-major projected q (scaled)
__device__ uint32_t g_kf[HEADS * NCHUNK * 1024];   // fragment-major fp16 K
__device__ uint32_t g_vf[HEADS * NCHUNK * 1024];   // fragment-major fp16 V
// split-K partials (fp32)
__device__ float g_pm[NSPLIT * HEADS * N];
__device__ float g_pl[NSPLIT * HEADS * N];
__device__ float g_pav[NSPLIT * HEADS * N * DK];

// -------------------- helpers ---------------------------------------------
__device__ __forceinline__ uint32_t f2tf(float f) {
    uint32_t u;
    asm("cvt.rna.tf32.f32 %0, %1;" : "=r"(u) : "f"(f));
    return u;
}

__device__ __forceinline__ uint32_t packh2(float lo, float hi) {
    __half2 h = __floats2half2_rn(lo, hi);
    return *reinterpret_cast<uint32_t*>(&h);
}

__device__ __forceinline__ void mma_tf32(float& d0, float& d1, float& d2, float& d3,
                                         uint32_t a0, uint32_t a1, uint32_t a2, uint32_t a3,
                                         uint32_t b0, uint32_t b1)
{
    asm volatile("mma.sync.aligned.m16n8k8.row.col.f32.tf32.tf32.f32 "
                 "{%0,%1,%2,%3}, {%4,%5,%6,%7}, {%8,%9}, {%0,%1,%2,%3};"
                 : "+f"(d0), "+f"(d1), "+f"(d2), "+f"(d3)
                 : "r"(a0), "r"(a1), "r"(a2), "r"(a3), "r"(b0), "r"(b1));
}

__device__ __forceinline__ void mma_f16(float& d0, float& d1, float& d2, float& d3,
                                        uint32_t a0, uint32_t a1, uint32_t a2, uint32_t a3,
                                        uint32_t b0, uint32_t b1)
{
    asm volatile("mma.sync.aligned.m16n8k16.row.col.f32.f16.f16.f32 "
                 "{%0,%1,%2,%3}, {%4,%5,%6,%7}, {%8,%9}, {%0,%1,%2,%3};"
                 : "+f"(d0), "+f"(d1), "+f"(d2), "+f"(d3)
                 : "r"(a0), "r"(a1), "r"(a2), "r"(a3), "r"(b0), "r"(b1));
}

__device__ __forceinline__ void cp16(uint32_t smem_dst, const void* gsrc) {
    asm volatile("cp.async.cg.shared.global [%0], [%1], 16;"
                 :: "r"(smem_dst), "l"(gsrc));
}

// K fragment word index (fp16x2 packed over d-pairs): B-frag of m16n8k16
__device__ __forceinline__ int kaddr16(int key, int d) {
    return ((d >> 4) * 8 + (key >> 3)) * 64 + ((key & 7) * 4 + ((d & 7) >> 1)) * 2 + ((d >> 3) & 1);
}
// V fragment half index (fp16x2 packed over key-pairs)
__device__ __forceinline__ int vaddr16h(int key, int d) {
    return ((((key >> 4) * 4 + (d >> 3)) * 32 + (d & 7) * 4 + ((key & 7) >> 1)) * 2
            + ((key >> 3) & 1)) * 2 + (key & 1);
}

// -------------------- tf32 projection GEMM body ----------------------------
__device__ __forceinline__ void proj_body(const float* __restrict__ A,
                                          const float* __restrict__ W,
                                          const float* __restrict__ bias,
                                          float* __restrict__ out,
                                          float scale, int mode, int m0, int n0)
{
    __shared__ uint4 AF[2][16 * 32];
    __shared__ uint2 BF[2][32 * 32];

    const int t    = threadIdx.x;
    const int lane = t & 31;
    const int w    = t >> 5;
    const int q    = lane & 3;
    const int g    = lane >> 2;
    const int mf    = w >> 1;
    const int nhalf = w & 1;

    float acc[4][4];
    #pragma unroll
    for (int j = 0; j < 4; j++)
        #pragma unroll
        for (int e = 0; e < 4; e++) acc[j][e] = 0.f;

    const int a_m0 = t >> 3,         a_k4_0 = t & 7;
    const int a_m1 = (t + 256) >> 3, a_k4_1 = (t + 256) & 7;
    const int b_k0 = t >> 4,         b_n4_0 = t & 15;
    const int b_k1 = (t + 256) >> 4, b_n4_1 = (t + 256) & 15;

    float4 ra0, ra1, rb0, rb1;
    ra0 = *(const float4*)&A[(size_t)(m0 + a_m0) * 256 + 0 + a_k4_0 * 4];
    ra1 = *(const float4*)&A[(size_t)(m0 + a_m1) * 256 + 0 + a_k4_1 * 4];
    rb0 = *(const float4*)&W[(size_t)(0 + b_k0) * 256 + n0 + b_n4_0 * 4];
    rb1 = *(const float4*)&W[(size_t)(0 + b_k1) * 256 + n0 + b_n4_1 * 4];

    for (int c = 0; c < 8; c++) {
        const int buf = c & 1;
        {
            #pragma unroll
            for (int p = 0; p < 2; p++) {
                int m  = p ? a_m1 : a_m0;
                int k4 = p ? a_k4_1 : a_k4_0;
                float4 v = p ? ra1 : ra0;
                int frag = (m >> 4) * 4 + (k4 >> 1);
                int idx  = (k4 & 1) * 2 + ((m & 15) >> 3);
                uint32_t* dst = (uint32_t*)&AF[buf][frag * 32 + ((m & 7) * 4)];
                dst[0 * 4 + idx] = f2tf(v.x);
                dst[1 * 4 + idx] = f2tf(v.y);
                dst[2 * 4 + idx] = f2tf(v.z);
                dst[3 * 4 + idx] = f2tf(v.w);
            }
            #pragma unroll
            for (int p = 0; p < 2; p++) {
                int k  = p ? b_k1 : b_k0;
                int n4 = p ? b_n4_1 : b_n4_0;
                float4 v = p ? rb1 : rb0;
                int frag = (n4 >> 1) * 4 + (k >> 3);
                int hi   = (k >> 2) & 1;
                uint32_t* dst = (uint32_t*)&BF[buf][frag * 32 + (n4 & 1) * 16 + (k & 3)];
                dst[0 * 8 + hi] = f2tf(v.x);
                dst[1 * 8 + hi] = f2tf(v.y);
                dst[2 * 8 + hi] = f2tf(v.z);
                dst[3 * 8 + hi] = f2tf(v.w);
            }
        }
        __syncthreads();

        if (c < 7) {
            int kt = (c + 1) * 32;
            ra0 = *(const float4*)&A[(size_t)(m0 + a_m0) * 256 + kt + a_k4_0 * 4];
            ra1 = *(const float4*)&A[(size_t)(m0 + a_m1) * 256 + kt + a_k4_1 * 4];
            rb0 = *(const float4*)&W[(size_t)(kt + b_k0) * 256 + n0 + b_n4_0 * 4];
            rb1 = *(const float4*)&W[(size_t)(kt + b_k1) * 256 + n0 + b_n4_1 * 4];
        }

        #pragma unroll
        for (int ks = 0; ks < 4; ks++) {
            uint4 a = AF[buf][(mf * 4 + ks) * 32 + lane];
            #pragma unroll
            for (int j = 0; j < 4; j++) {
                uint2 b = BF[buf][((nhalf * 4 + j) * 4 + ks) * 32 + lane];
                mma_tf32(acc[j][0], acc[j][1], acc[j][2], acc[j][3],
                         a.x, a.y, a.z, a.w, b.x, b.y);
            }
        }
    }

    const int row0 = m0 + mf * 16 + g;
    const int key0 = mf * 16 + g;
    const int ck   = m0 >> 6;
    #pragma unroll
    for (int j = 0; j < 4; j++) {
        int col = n0 + nhalf * 32 + j * 8 + 2 * q;
        float2 bz = *(const float2*)&bias[col];
        float v00 = acc[j][0] + bz.x, v01 = acc[j][1] + bz.y;
        float v10 = acc[j][2] + bz.x, v11 = acc[j][3] + bz.y;
        if (mode == 0) {
            v00 *= scale; v01 *= scale; v10 *= scale; v11 *= scale;
            size_t base = (size_t)(col >> 5) * ((size_t)N * 32) + (col & 31);
            *(float2*)&out[base + (size_t)row0 * 32]       = make_float2(v00, v01);
            *(float2*)&out[base + (size_t)(row0 + 8) * 32] = make_float2(v10, v11);
        } else {
            int hh = col >> 5, dd = col & 31;
            if (mode == 2) {
                uint32_t* KD = &g_kf[((size_t)hh * NCHUNK + ck) * 1024];
                KD[kaddr16(key0,     dd)] = packh2(v00, v01);
                KD[kaddr16(key0 + 8, dd)] = packh2(v10, v11);
            } else {
                __half* VD = (__half*)&g_vf[((size_t)hh * NCHUNK + ck) * 1024];
                VD[vaddr16h(key0,     dd)]     = __float2half_rn(v00);
                VD[vaddr16h(key0,     dd + 1)] = __float2half_rn(v01);
                VD[vaddr16h(key0 + 8, dd)]     = __float2half_rn(v10);
                VD[vaddr16h(key0 + 8, dd + 1)] = __float2half_rn(v11);
            }
        }
    }
}

// -------------------- fused prep: QKV projections + pair-bias --------------
// Blocks [0,384): tf32 Q/K/V projection tiles (tensor/latency-bound).
// Blocks [384, 1408): fp16 bias stream with 4x per-thread ILP.
__global__ __launch_bounds__(256) void prep_kernel(
    const float* __restrict__ q, const float* __restrict__ k, const float* __restrict__ v,
    const float* __restrict__ Wq, const float* __restrict__ Wk, const float* __restrict__ Wv,
    const float* __restrict__ bq, const float* __restrict__ bk, const float* __restrict__ bv,
    float* __restrict__ oq, float scale,
    const int* __restrict__ label, const float* __restrict__ dist,
    const float* __restrict__ contact,
    const float* __restrict__ Wd1, const float* __restrict__ bd1,
    const float* __restrict__ Wd2, const float* __restrict__ bd2,
    const float* __restrict__ Wc1, const float* __restrict__ bc1,
    const float* __restrict__ Wc2, const float* __restrict__ bc2)
{
    const int bid = blockIdx.x;
    if (bid < PROJ_BLOCKS) {
        const int pz  = bid >> 7;
        const int rem = bid & 127;
        const int m0  = (rem & 31) * 64;
        const int n0  = (rem >> 5) * 64;
        if (pz == 0)      proj_body(q, Wq, bq, oq,      scale, 0, m0, n0);
        else if (pz == 1) proj_body(k, Wk, bk, nullptr, 1.f,   2, m0, n0);
        else              proj_body(v, Wv, bv, nullptr, 1.f,   3, m0, n0);
        return;
    }

    // ---- bias path (4x ILP: 12 independent LDG.128 in flight) ----
    __shared__ float4 cf;
    if (threadIdx.x == 0) {
        float am = 0.f, al = 0.f, c0 = bd2[0] + bc2[0], cm = 0.f;
        #pragma unroll
        for (int h = 0; h < 16; h++) {
            am += Wd1[h]      * Wd2[h];
            al += Wd1[16 + h] * Wd2[h];
            c0 += bd1[h]      * Wd2[h];
            cm += Wc1[h]      * Wc2[h];
            al += Wc1[16 + h] * Wc2[h];
            c0 += bc1[h]      * Wc2[h];
        }
        cf = make_float4(am, cm, al, c0);
    }

    const int base = (bid - PROJ_BLOCKS) * 256 * BIAS_ILP + threadIdx.x;
    float4 dm[BIAS_ILP], cv[BIAS_ILP];
    int4   lb[BIAS_ILP];
    #pragma unroll
    for (int u = 0; u < BIAS_ILP; u++) {
        int i = base + u * 256;
        dm[u] = ((const float4*)dist)[i];
        cv[u] = ((const float4*)contact)[i];
        lb[u] = ((const int4*)label)[i];
    }
    __syncthreads();
    const float am = cf.x, cm = cf.y, al = cf.z, c0 = cf.w;

    #pragma unroll
    for (int u = 0; u < BIAS_ILP; u++) {
        float ox = fmaf(am, dm[u].x, fmaf(cm, cv[u].x, fmaf(al, (float)lb[u].x, c0)));
        float oy = fmaf(am, dm[u].y, fmaf(cm, cv[u].y, fmaf(al, (float)lb[u].y, c0)));
        float oz = fmaf(am, dm[u].z, fmaf(cm, cv[u].z, fmaf(al, (float)lb[u].z, c0)));
        float ow = fmaf(am, dm[u].w, fmaf(cm, cv[u].w, fmaf(al, (float)lb[u].w, c0)));
        uint2 r;
        r.x = packh2(ox, oy);
        r.y = packh2(oz, ow);
        ((uint2*)g_bias)[base + u * 256] = r;
    }
}

// -------------------- O-projection with fused 2-way split-K combine --------
__global__ __launch_bounds__(256) void o_proj_fused(const float* __restrict__ W,
                                                    const float* __restrict__ bo,
                                                    float* __restrict__ out)
{
    __shared__ uint4 AF[2][16 * 32];
    __shared__ uint2 BF[2][32 * 32];
    __shared__ float2 WC[64][8];

    const int t    = threadIdx.x;
    const int lane = t & 31;
    const int w    = t >> 5;
    const int q    = lane & 3;
    const int g    = lane >> 2;
    const int m0   = blockIdx.x * 64;
    const int n0   = blockIdx.y * 64;
    const int mf    = w >> 1;
    const int nhalf = w & 1;

    #pragma unroll
    for (int p = 0; p < 2; p++) {
        int idx = t + p * 256;
        int r = idx >> 3, hh = idx & 7;
        int row = m0 + r;
        float pm0 = g_pm[(0 * HEADS + hh) * N + row];
        float pm1 = g_pm[(1 * HEADS + hh) * N + row];
        float pl0 = g_pl[(0 * HEADS + hh) * N + row];
        float pl1 = g_pl[(1 * HEADS + hh) * N + row];
        float M = fmaxf(pm0, pm1);
        float w0 = __expf(pm0 - M), w1 = __expf(pm1 - M);
        float inv = 1.f / (pl0 * w0 + pl1 * w1);
        WC[r][hh] = make_float2(w0 * inv, w1 * inv);
    }
    __syncthreads();

    float acc[4][4];
    #pragma unroll
    for (int j = 0; j < 4; j++)
        #pragma unroll
        for (int e = 0; e < 4; e++) acc[j][e] = 0.f;

    const int a_m0 = t >> 3,         a_k4_0 = t & 7;
    const int a_m1 = (t + 256) >> 3, a_k4_1 = (t + 256) & 7;
    const int b_k0 = t >> 4,         b_n4_0 = t & 15;
    const int b_k1 = (t + 256) >> 4, b_n4_1 = (t + 256) & 15;

    float4 pv[2][2];
    float4 rb0, rb1;
    #pragma unroll
    for (int p = 0; p < 2; p++) {
        int m  = p ? a_m1 : a_m0;
        int d0 = (p ? a_k4_1 : a_k4_0) * 4;
        #pragma unroll
        for (int s = 0; s < NSPLIT; s++)
            pv[p][s] = *(const float4*)&g_pav[(((size_t)(s * HEADS + 0)) * N + m0 + m) * DK + d0];
    }
    rb0 = *(const float4*)&W[(size_t)(0 + b_k0) * 256 + n0 + b_n4_0 * 4];
    rb1 = *(const float4*)&W[(size_t)(0 + b_k1) * 256 + n0 + b_n4_1 * 4];

    for (int c = 0; c < 8; c++) {
        const int buf = c & 1;
        {
            #pragma unroll
            for (int p = 0; p < 2; p++) {
                int m  = p ? a_m1 : a_m0;
                int k4 = p ? a_k4_1 : a_k4_0;
                float2 wc = WC[m][c];
                float4 v;
                v.x = wc.x * pv[p][0].x + wc.y * pv[p][1].x;
                v.y = wc.x * pv[p][0].y + wc.y * pv[p][1].y;
                v.z = wc.x * pv[p][0].z + wc.y * pv[p][1].z;
                v.w = wc.x * pv[p][0].w + wc.y * pv[p][1].w;
                int frag = (m >> 4) * 4 + (k4 >> 1);
                int idx  = (k4 & 1) * 2 + ((m & 15) >> 3);
                uint32_t* dst = (uint32_t*)&AF[buf][frag * 32 + ((m & 7) * 4)];
                dst[0 * 4 + idx] = f2tf(v.x);
                dst[1 * 4 + idx] = f2tf(v.y);
                dst[2 * 4 + idx] = f2tf(v.z);
                dst[3 * 4 + idx] = f2tf(v.w);
            }
            #pragma unroll
            for (int p = 0; p < 2; p++) {
                int k  = p ? b_k1 : b_k0;
                int n4 = p ? b_n4_1 : b_n4_0;
                float4 v = p ? rb1 : rb0;
                int frag = (n4 >> 1) * 4 + (k >> 3);
                int hi   = (k >> 2) & 1;
                uint32_t* dst = (uint32_t*)&BF[buf][frag * 32 + (n4 & 1) * 16 + (k & 3)];
                dst[0 * 8 + hi] = f2tf(v.x);
                dst[1 * 8 + hi] = f2tf(v.y);
                dst[2 * 8 + hi] = f2tf(v.z);
                dst[3 * 8 + hi] = f2tf(v.w);
            }
        }
        __syncthreads();

        if (c < 7) {
            int hh = c + 1;
            #pragma unroll
            for (int p = 0; p < 2; p++) {
                int m  = p ? a_m1 : a_m0;
                int d0 = (p ? a_k4_1 : a_k4_0) * 4;
                #pragma unroll
                for (int s = 0; s < NSPLIT; s++)
                    pv[p][s] = *(const float4*)&g_pav[(((size_t)(s * HEADS + hh)) * N + m0 + m) * DK + d0];
            }
            int kt = hh * 32;
            rb0 = *(const float4*)&W[(size_t)(kt + b_k0) * 256 + n0 + b_n4_0 * 4];
            rb1 = *(const float4*)&W[(size_t)(kt + b_k1) * 256 + n0 + b_n4_1 * 4];
        }

        #pragma unroll
        for (int ks = 0; ks < 4; ks++) {
            uint4 a = AF[buf][(mf * 4 + ks) * 32 + lane];
            #pragma unroll
            for (int j = 0; j < 4; j++) {
                uint2 b = BF[buf][((nhalf * 4 + j) * 4 + ks) * 32 + lane];
                mma_tf32(acc[j][0], acc[j][1], acc[j][2], acc[j][3],
                         a.x, a.y, a.z, a.w, b.x, b.y);
            }
        }
    }

    const int row0 = m0 + mf * 16 + g;
    #pragma unroll
    for (int j = 0; j < 4; j++) {
        int col = n0 + nhalf * 32 + j * 8 + 2 * q;
        float2 bz = *(const float2*)&bo[col];
        *(float2*)&out[(size_t)row0 * 256 + col] =
            make_float2(acc[j][0] + bz.x, acc[j][1] + bz.y);
        *(float2*)&out[(size_t)(row0 + 8) * 256 + col] =
            make_float2(acc[j][2] + bz.x, acc[j][3] + bz.y);
    }
}

// -------------------- fp16 flash attention (R9 shape, NSPLIT=2) ------------
__global__ __launch_bounds__(128) void attn_mma_kernel()
{
    extern __shared__ uint32_t dsm[];
    uint32_t* KBb = dsm;                     // [2][1024]
    uint32_t* VBb = dsm + 2048;              // [2][1024]
    __half*   BSb = (__half*)(dsm + 4096);   // [2][64*BSTR]

    const int tid  = threadIdx.x;
    const int lane = tid & 31;
    const int warp = tid >> 5;
    const int q    = lane & 3;
    const int g    = lane >> 2;
    const int h  = blockIdx.y;
    const int z  = blockIdx.z;
    const int q0 = blockIdx.x * 64;
    const int wr0 = warp * 16;
    const int row = q0 + wr0 + g;

    uint32_t qa[2][4];
    {
        const float* q0p = &g_qh[((size_t)h * N + row) * DK];
        const float* q8p = q0p + 8 * DK;
        #pragma unroll
        for (int ks = 0; ks < 2; ks++) {
            int d = ks * 16 + 2 * q;
            qa[ks][0] = packh2(q0p[d],     q0p[d + 1]);
            qa[ks][1] = packh2(q8p[d],     q8p[d + 1]);
            qa[ks][2] = packh2(q0p[d + 8], q0p[d + 9]);
            qa[ks][3] = packh2(q8p[d + 8], q8p[d + 9]);
        }
    }

    float o[4][4];
    #pragma unroll
    for (int n = 0; n < 4; n++)
        #pragma unroll
        for (int e = 0; e < 4; e++) o[n][e] = 0.f;

    float m0 = -INFINITY, m8 = -INFINITY, l0 = 0.f, l8 = 0.f;

    const int ck0 = (z * KSPAN) / 64;
    const int nch = KSPAN / 64;

    auto fill = [&](int buf, int ck) {
        const uint4* ks = (const uint4*)&g_kf[(size_t)(h * NCHUNK + ck) * 1024];
        const uint4* vs = (const uint4*)&g_vf[(size_t)(h * NCHUNK + ck) * 1024];
        #pragma unroll
        for (int i = 0; i < 2; i++) {
            int idx = i * 128 + tid;
            cp16((uint32_t)__cvta_generic_to_shared(&KBb[buf * 1024 + idx * 4]), ks + idx);
            cp16((uint32_t)__cvta_generic_to_shared(&VBb[buf * 1024 + idx * 4]), vs + idx);
        }
        const __half* bsrc = &g_bias[(size_t)q0 * N + ck * 64];
        __half* bdst = &BSb[buf * 64 * BSTR];
        #pragma unroll
        for (int i = 0; i < 4; i++) {
            int idx = i * 128 + tid;
            int r = idx >> 3, c8 = idx & 7;
            cp16((uint32_t)__cvta_generic_to_shared(&bdst[r * BSTR + c8 * 8]),
                 &bsrc[(size_t)r * N + c8 * 8]);
        }
    };

    fill(0, ck0);
    asm volatile("cp.async.commit_group;");

    for (int cc = 0; cc < nch; cc++) {
        const int cur = cc & 1;

        if (cc + 1 < nch) {
            fill(1 - cur, ck0 + cc + 1);
            asm volatile("cp.async.commit_group;");
            asm volatile("cp.async.wait_group 1;");
        } else {
            asm volatile("cp.async.wait_group 0;");
        }
        __syncthreads();

        const uint32_t* KBc = &KBb[cur * 1024];
        const uint32_t* VBc = &VBb[cur * 1024];
        const __half*   BSc = &BSb[cur * 64 * BSTR];

        float s[8][4];
        #pragma unroll
        for (int j = 0; j < 8; j++)
            #pragma unroll
            for (int e = 0; e < 4; e++) s[j][e] = 0.f;

        #pragma unroll
        for (int ks = 0; ks < 2; ks++) {
            #pragma unroll
            for (int j = 0; j < 8; j++) {
                uint2 b = *(const uint2*)&KBc[((ks * 8 + j) * 32 + lane) * 2];
                mma_f16(s[j][0], s[j][1], s[j][2], s[j][3],
                        qa[ks][0], qa[ks][1], qa[ks][2], qa[ks][3], b.x, b.y);
            }
        }

        {
            const __half* br0 = &BSc[(wr0 + g) * BSTR];
            const __half* br8 = br0 + 8 * BSTR;
            #pragma unroll
            for (int j = 0; j < 8; j++) {
                float2 b0 = __half22float2(*(const __half2*)&br0[8 * j + 2 * q]);
                float2 b8 = __half22float2(*(const __half2*)&br8[8 * j + 2 * q]);
                s[j][0] += b0.x; s[j][1] += b0.y;
                s[j][2] += b8.x; s[j][3] += b8.y;
            }
        }

        float mx0 = s[0][0], mx8 = s[0][2];
        #pragma unroll
        for (int j = 0; j < 8; j++) {
            mx0 = fmaxf(mx0, fmaxf(s[j][0], s[j][1]));
            mx8 = fmaxf(mx8, fmaxf(s[j][2], s[j][3]));
        }
        mx0 = fmaxf(mx0, __shfl_xor_sync(0xffffffffu, mx0, 1));
        mx0 = fmaxf(mx0, __shfl_xor_sync(0xffffffffu, mx0, 2));
        mx8 = fmaxf(mx8, __shfl_xor_sync(0xffffffffu, mx8, 1));
        mx8 = fmaxf(mx8, __shfl_xor_sync(0xffffffffu, mx8, 2));

        float mn0 = fmaxf(m0, mx0), mn8 = fmaxf(m8, mx8);
        float c0 = __expf(m0 - mn0), c8 = __expf(m8 - mn8);
        m0 = mn0; m8 = mn8;
        l0 *= c0;  l8 *= c8;
        #pragma unroll
        for (int n = 0; n < 4; n++) {
            o[n][0] *= c0; o[n][1] *= c0;
            o[n][2] *= c8; o[n][3] *= c8;
        }

        float p[8][4];
        #pragma unroll
        for (int j = 0; j < 8; j++) {
            p[j][0] = __expf(s[j][0] - m0);
            p[j][1] = __expf(s[j][1] - m0);
            p[j][2] = __expf(s[j][2] - m8);
            p[j][3] = __expf(s[j][3] - m8);
            l0 += p[j][0] + p[j][1];
            l8 += p[j][2] + p[j][3];
        }

        #pragma unroll
        for (int kk = 0; kk < 4; kk++) {
            uint32_t a0 = packh2(p[2 * kk][0],     p[2 * kk][1]);
            uint32_t a1 = packh2(p[2 * kk][2],     p[2 * kk][3]);
            uint32_t a2 = packh2(p[2 * kk + 1][0], p[2 * kk + 1][1]);
            uint32_t a3 = packh2(p[2 * kk + 1][2], p[2 * kk + 1][3]);
            #pragma unroll
            for (int n = 0; n < 4; n++) {
                uint2 b = *(const uint2*)&VBc[((kk * 4 + n) * 32 + lane) * 2];
                mma_f16(o[n][0], o[n][1], o[n][2], o[n][3], a0, a1, a2, a3, b.x, b.y);
            }
        }
        __syncthreads();
    }

    l0 += __shfl_xor_sync(0xffffffffu, l0, 1);
    l0 += __shfl_xor_sync(0xffffffffu, l0, 2);
    l8 += __shfl_xor_sync(0xffffffffu, l8, 1);
    l8 += __shfl_xor_sync(0xffffffffu, l8, 2);

    const int rid = (z * HEADS + h) * N + q0 + wr0 + g;
    if (q == 0) {
        g_pm[rid] = m0;     g_pl[rid] = l0;
        g_pm[rid + 8] = m8; g_pl[rid + 8] = l8;
    }
    float* pav0 = &g_pav[(size_t)rid * DK];
    float* pav8 = &g_pav[(size_t)(rid + 8) * DK];
    #pragma unroll
    for (int n = 0; n < 4; n++) {
        *(float2*)&pav0[8 * n + 2 * q] = make_float2(o[n][0], o[n][1]);
        *(float2*)&pav8[8 * n + 2 * q] = make_float2(o[n][2], o[n][3]);
    }
}

// -------------------- launch ------------------------------------------------
extern "C" void kernel_launch(void* const* d_in, const int* in_sizes, int n_in,
                              void* d_out, int out_size)
{
    const int*   label   = (const int*)  d_in[0];
    const float* dist    = (const float*)d_in[1];
    const float* contact = (const float*)d_in[2];
    const float* q       = (const float*)d_in[3];
    const float* k       = (const float*)d_in[4];
    const float* v       = (const float*)d_in[5];
    const float* Wq = (const float*)d_in[6];  const float* bq = (const float*)d_in[7];
    const float* Wk = (const float*)d_in[8];  const float* bk = (const float*)d_in[9];
    const float* Wv = (const float*)d_in[10]; const float* bv = (const float*)d_in[11];
    const float* Wo = (const float*)d_in[12]; const float* bo = (const float*)d_in[13];
    const float* Wd1 = (const float*)d_in[14]; const float* bd1 = (const float*)d_in[15];
    const float* Wd2 = (const float*)d_in[16]; const float* bd2 = (const float*)d_in[17];
    const float* Wc1 = (const float*)d_in[18]; const float* bc1 = (const float*)d_in[19];
    const float* Wc2 = (const float*)d_in[20]; const float* bc2 = (const float*)d_in[21];
    float* out = (float*)d_out;

    float* p_qh;
    cudaGetSymbolAddress((void**)&p_qh, g_qh);

    const float scale = 1.f / sqrtf((float)DK);
    prep_kernel<<<PROJ_BLOCKS + BIAS_BLOCKS, 256>>>(
        q, k, v, Wq, Wk, Wv, bq, bk, bv, p_qh, scale,
        label, dist, contact, Wd1, bd1, Wd2, bd2, Wc1, bc1, Wc2, bc2);

    const int attn_smem = 4096 * 4 + 2 * 64 * BSTR * 2;   // 34816 B
    static int smem_set = 0;
    if (!smem_set) {
        cudaFuncSetAttribute(attn_mma_kernel,
                             cudaFuncAttributeMaxDynamicSharedMemorySize, attn_smem);
        smem_set = 1;
    }
    attn_mma_kernel<<<dim3(N / 64, HEADS, NSPLIT), 128, attn_smem>>>();

    o_proj_fused<<<dim3(N / 64, HIDDEN / 64), 256>>>(Wo, bo, out);
}